// round 14
// baseline (speedup 1.0000x reference)
#include <cuda_runtime.h>
#include <math.h>
#include <stdint.h>

#define B_  2
#define S_  2048
#define D_  1024
#define H_  16
#define HD_ 64
#define M_  (B_ * S_)    // 4096
#define N3_ (3 * D_)     // 3072

// Scratch for Q/K/V in (b*H+h, s, e) layout. All tf32-rounded.
__device__ float g_Q[(size_t)M_ * D_];      // tf32-rounded, pre-scaled by QSCALE
__device__ float g_K[(size_t)M_ * D_];      // tf32-rounded
__device__ float g_V[(size_t)M_ * D_];      // tf32-rounded

// ---------------------------------------------------------------------------
// TF32 helpers
// ---------------------------------------------------------------------------
__device__ __forceinline__ uint32_t f2tf(float x) {
    uint32_t r;
    asm("cvt.rna.tf32.f32 %0, %1;" : "=r"(r) : "f"(x));
    return r;
}
__device__ __forceinline__ float tf32r(float x) {
    uint32_t r;
    asm("cvt.rna.tf32.f32 %0, %1;" : "=r"(r) : "f"(x));
    return __uint_as_float(r);
}
__device__ __forceinline__ float ex2(float x) {
    float r;
    asm("ex2.approx.f32 %0, %1;" : "=f"(r) : "f"(x));
    return r;
}
__device__ __forceinline__ void mma_tf32(float c[4],
    uint32_t a0, uint32_t a1, uint32_t a2, uint32_t a3,
    uint32_t b0, uint32_t b1)
{
    asm volatile(
        "mma.sync.aligned.m16n8k8.row.col.f32.tf32.tf32.f32 "
        "{%0,%1,%2,%3}, {%4,%5,%6,%7}, {%8,%9}, {%0,%1,%2,%3};"
        : "+f"(c[0]), "+f"(c[1]), "+f"(c[2]), "+f"(c[3])
        : "r"(a0), "r"(a1), "r"(a2), "r"(a3), "r"(b0), "r"(b1));
}

// Q scale: 1/sqrt(64) * log2(e) -> scores in log2 domain, softmax via ex2
#define QSCALE 0.1803368801111204f

// ---------------------------------------------------------------------------
// Kernel 1: QKV projection, single-pass TF32 MMA (UNCHANGED from R12 — 217us).
// BM=128, BN=128, BK=16, 256 threads, warps 4(M)x2(N), warp tile 32x64.
// ---------------------------------------------------------------------------
#define GP_A 20
#define GP_W 136

__global__ __launch_bounds__(256, 2) void qkv_mma_kernel(
    const float* __restrict__ A, const float* __restrict__ W,
    const float* __restrict__ qbias, const float* __restrict__ vbias)
{
    __shared__ float Ahi[128 * GP_A];   // 10240 B
    __shared__ float Whi[16 * GP_W];    // 8704 B

    const int tid  = threadIdx.x;
    const int warp = tid >> 5;
    const int lane = tid & 31;
    const int g    = lane >> 2;
    const int t    = lane & 3;
    const int bm   = blockIdx.y * 128;
    const int bn   = blockIdx.x * 128;
    const int warpM = (warp >> 1) * 32;
    const int warpN = (warp & 1) * 64;

    float C[2][8][4];
    #pragma unroll
    for (int mf = 0; mf < 2; mf++)
        #pragma unroll
        for (int nf = 0; nf < 8; nf++)
            #pragma unroll
            for (int j = 0; j < 4; j++) C[mf][nf][j] = 0.f;

    int arow[2], acg[2], wkk[2], wnn[2];
    float4 pa[2], pw[2];
    #pragma unroll
    for (int i = 0; i < 2; i++) {
        int idx = tid + i * 256;
        arow[i] = idx >> 2;
        acg[i]  = (idx & 3) << 2;
        wkk[i]  = idx >> 5;
        wnn[i]  = (idx & 31) << 2;
        pa[i] = *(const float4*)(A + (size_t)(bm + arow[i]) * D_ + acg[i]);
        pw[i] = *(const float4*)(W + (size_t)wkk[i] * N3_ + bn + wnn[i]);
    }

    for (int k0 = 0; k0 < D_ / 16; k0++) {
        __syncthreads();

        #pragma unroll
        for (int i = 0; i < 2; i++) {
            float4 x = pa[i];
            *(float4*)&Ahi[arow[i] * GP_A + acg[i]] =
                make_float4(tf32r(x.x), tf32r(x.y), tf32r(x.z), tf32r(x.w));
            float4 y = pw[i];
            *(float4*)&Whi[wkk[i] * GP_W + wnn[i]] =
                make_float4(tf32r(y.x), tf32r(y.y), tf32r(y.z), tf32r(y.w));
        }
        __syncthreads();

        if (k0 < D_ / 16 - 1) {
            #pragma unroll
            for (int i = 0; i < 2; i++) {
                pa[i] = *(const float4*)(A + (size_t)(bm + arow[i]) * D_
                                           + (k0 + 1) * 16 + acg[i]);
                pw[i] = *(const float4*)(W + (size_t)((k0 + 1) * 16 + wkk[i]) * N3_
                                           + bn + wnn[i]);
            }
        }

        #pragma unroll
        for (int kc = 0; kc < 2; kc++) {
            uint32_t ah[2][4];
            #pragma unroll
            for (int mf = 0; mf < 2; mf++) {
                int r0 = (warpM + mf * 16 + g) * GP_A + kc * 8 + t;
                ah[mf][0] = __float_as_uint(Ahi[r0]);
                ah[mf][1] = __float_as_uint(Ahi[r0 + 8 * GP_A]);
                ah[mf][2] = __float_as_uint(Ahi[r0 + 4]);
                ah[mf][3] = __float_as_uint(Ahi[r0 + 8 * GP_A + 4]);
            }
            #pragma unroll
            for (int nf = 0; nf < 8; nf++) {
                int n  = warpN + nf * 8 + g;
                int kb = (kc * 8 + t) * GP_W + n;
                uint32_t bh0 = __float_as_uint(Whi[kb]);
                uint32_t bh1 = __float_as_uint(Whi[kb + 4 * GP_W]);
                #pragma unroll
                for (int mf = 0; mf < 2; mf++)
                    mma_tf32(C[mf][nf], ah[mf][0], ah[mf][1], ah[mf][2], ah[mf][3], bh0, bh1);
            }
        }
    }

    const int which = bn >> 10;
    #pragma unroll
    for (int mf = 0; mf < 2; mf++) {
        int mrow = bm + warpM + mf * 16 + g;
        int b = mrow >> 11;
        int s = mrow & (S_ - 1);
        #pragma unroll
        for (int nf = 0; nf < 8; nf++) {
            int ncol = bn + warpN + nf * 8 + 2 * t;
            int d = ncol & (D_ - 1);
            int h = d >> 6;
            int e = d & 63;
            size_t i0 = ((size_t)(b * H_ + h) * S_ + s) * HD_ + e;
            size_t i1 = i0 + 8 * HD_;
            float c0 = C[mf][nf][0], c1 = C[mf][nf][1];
            float c2 = C[mf][nf][2], c3 = C[mf][nf][3];
            if (which == 0) {
                float b0 = qbias[d], b1 = qbias[d + 1];
                *(float2*)&g_Q[i0] = make_float2(tf32r((c0 + b0) * QSCALE),
                                                 tf32r((c1 + b1) * QSCALE));
                *(float2*)&g_Q[i1] = make_float2(tf32r((c2 + b0) * QSCALE),
                                                 tf32r((c3 + b1) * QSCALE));
            } else if (which == 1) {
                *(float2*)&g_K[i0] = make_float2(tf32r(c0), tf32r(c1));
                *(float2*)&g_K[i1] = make_float2(tf32r(c2), tf32r(c3));
            } else {
                float b0 = vbias[d], b1 = vbias[d + 1];
                *(float2*)&g_V[i0] = make_float2(tf32r(c0 + b0), tf32r(c1 + b1));
                *(float2*)&g_V[i1] = make_float2(tf32r(c2 + b0), tf32r(c3 + b1));
            }
        }
    }
}

// ---------------------------------------------------------------------------
// Kernel 2: flash attention, single-MMA QK/PV, 8 warps x M=16 warp tile.
// Occupancy play: regs halve (Sf/O 32+32 floats) -> 2 blocks x 8 warps =
// 16 warps/SM (4/SMSP), doubling latency hiding vs the 4-warp M=32 version.
// Br=128, Bc=64; blocking LDG staging (cp.async regressed in R13).
// smem: Qs [128][68] + Khi [64][68] + Vt [64][72] = 70656 B -> 2 blk/SM.
// Math per row identical to R12 attn7 -> rel_err should be unchanged.
// ---------------------------------------------------------------------------
#define QP 68
#define KP 68
#define VP 72
#define SM_Q (128 * QP)
#define SM_K (64 * KP)
#define SM_V (64 * VP)
#define ATTN_SMEM_BYTES ((SM_Q + SM_K + SM_V) * (int)sizeof(float))   // 70656

__global__ __launch_bounds__(256, 2) void attn9_kernel(float* __restrict__ out)
{
    extern __shared__ float sm[];
    float* Qs  = sm;             // [128][QP] tf32-rounded, pre-scaled
    float* Khi = Qs + SM_Q;      // [64][KP] tf32-rounded
    float* Vt  = Khi + SM_K;     // [64][VP] tf32-rounded

    const int tid  = threadIdx.x;
    const int warp = tid >> 5;
    const int lane = tid & 31;
    const int g    = lane >> 2;
    const int t    = lane & 3;
    const int wm   = warp * 16;    // warp's 16-row band
    const int bh   = blockIdx.y;
    const int qt   = blockIdx.x;

    const float* Qg = g_Q + ((size_t)bh * S_ + qt * 128) * HD_;
    const float* Kg = g_K + (size_t)bh * S_ * HD_;
    const float* Vg = g_V + (size_t)bh * S_ * HD_;

    // Load Q tile (128x64): 8 float4 per thread (256 threads)
    #pragma unroll
    for (int i = 0; i < 8; i++) {
        int idx = tid + i * 256;
        int row = idx >> 4;
        int col = (idx & 15) << 2;
        *(float4*)&Qs[row * QP + col] = *(const float4*)(Qg + row * HD_ + col);
    }

    float m0 = -INFINITY, m1 = -INFINITY, l0 = 0.f, l1 = 0.f;
    float O[8][4];
    #pragma unroll
    for (int nt = 0; nt < 8; nt++)
        #pragma unroll
        for (int j = 0; j < 4; j++) O[nt][j] = 0.f;

    for (int kt = 0; kt < S_ / 64; kt++) {
        __syncthreads();

        // ---- stage K and V: 4 float4 per thread each (256 threads) ----
        const float* Kt = Kg + (size_t)kt * 64 * HD_;
        const float* Vp = Vg + (size_t)kt * 64 * HD_;
        #pragma unroll
        for (int i = 0; i < 4; i++) {
            int idx = tid + i * 256;
            int row = idx >> 4;
            int col = (idx & 15) << 2;
            *(float4*)&Khi[row * KP + col] = *(const float4*)(Kt + row * HD_ + col);
            *(float4*)&Vt[row * VP + col]  = *(const float4*)(Vp + row * HD_ + col);
        }
        __syncthreads();

        // ---- scores (log2 domain): 1 MMA, fragments pure LDS ----
        float Sf[8][4];
        #pragma unroll
        for (int nt = 0; nt < 8; nt++)
            #pragma unroll
            for (int j = 0; j < 4; j++) Sf[nt][j] = 0.f;

        #pragma unroll
        for (int kc = 0; kc < 8; kc++) {
            int qi = (wm + g) * QP + kc * 8 + t;
            uint32_t a0 = __float_as_uint(Qs[qi]);
            uint32_t a1 = __float_as_uint(Qs[qi + 8 * QP]);
            uint32_t a2 = __float_as_uint(Qs[qi + 4]);
            uint32_t a3 = __float_as_uint(Qs[qi + 8 * QP + 4]);
            #pragma unroll
            for (int nt = 0; nt < 8; nt++) {
                int kb = (nt * 8 + g) * KP + kc * 8 + t;
                uint32_t bh0 = __float_as_uint(Khi[kb]);
                uint32_t bh1 = __float_as_uint(Khi[kb + 4]);
                mma_tf32(Sf[nt], a0, a1, a2, a3, bh0, bh1);
            }
        }

        // ---- online softmax (base-2), rows wm+g and wm+g+8 ----
        float mx0 = -INFINITY, mx1 = -INFINITY;
        #pragma unroll
        for (int nt = 0; nt < 8; nt++) {
            mx0 = fmaxf(mx0, fmaxf(Sf[nt][0], Sf[nt][1]));
            mx1 = fmaxf(mx1, fmaxf(Sf[nt][2], Sf[nt][3]));
        }
        mx0 = fmaxf(mx0, __shfl_xor_sync(0xffffffffu, mx0, 1));
        mx0 = fmaxf(mx0, __shfl_xor_sync(0xffffffffu, mx0, 2));
        mx1 = fmaxf(mx1, __shfl_xor_sync(0xffffffffu, mx1, 1));
        mx1 = fmaxf(mx1, __shfl_xor_sync(0xffffffffu, mx1, 2));

        float mn0 = fmaxf(m0, mx0);
        float mn1 = fmaxf(m1, mx1);
        float alp0 = ex2(m0 - mn0);
        float alp1 = ex2(m1 - mn1);

        float ls0 = 0.f, ls1 = 0.f;
        #pragma unroll
        for (int nt = 0; nt < 8; nt++) {
            Sf[nt][0] = ex2(Sf[nt][0] - mn0);
            Sf[nt][1] = ex2(Sf[nt][1] - mn0);
            Sf[nt][2] = ex2(Sf[nt][2] - mn1);
            Sf[nt][3] = ex2(Sf[nt][3] - mn1);
            ls0 += Sf[nt][0] + Sf[nt][1];
            ls1 += Sf[nt][2] + Sf[nt][3];
        }
        ls0 += __shfl_xor_sync(0xffffffffu, ls0, 1);
        ls0 += __shfl_xor_sync(0xffffffffu, ls0, 2);
        ls1 += __shfl_xor_sync(0xffffffffu, ls1, 1);
        ls1 += __shfl_xor_sync(0xffffffffu, ls1, 2);

        l0 = l0 * alp0 + ls0;  m0 = mn0;
        l1 = l1 * alp1 + ls1;  m1 = mn1;

        #pragma unroll
        for (int nt = 0; nt < 8; nt++) {
            O[nt][0] *= alp0;  O[nt][1] *= alp0;
            O[nt][2] *= alp1;  O[nt][3] *= alp1;
        }

        // ---- O += P @ V  (P tf32 via shuffles, V single-pass) ----
        const int src0 = (lane & ~3) + (t >> 1);
        const int src2 = src0 + 2;
        const bool odd = (t & 1);

        #pragma unroll
        for (int kc = 0; kc < 8; kc++) {
            float e0 = __shfl_sync(0xffffffffu, Sf[kc][0], src0);
            float e1 = __shfl_sync(0xffffffffu, Sf[kc][1], src0);
            float f0 = __shfl_sync(0xffffffffu, Sf[kc][0], src2);
            float f1 = __shfl_sync(0xffffffffu, Sf[kc][1], src2);
            float h0 = __shfl_sync(0xffffffffu, Sf[kc][2], src0);
            float h1 = __shfl_sync(0xffffffffu, Sf[kc][3], src0);
            float i0 = __shfl_sync(0xffffffffu, Sf[kc][2], src2);
            float i1 = __shfl_sync(0xffffffffu, Sf[kc][3], src2);
            uint32_t a0 = f2tf(odd ? e1 : e0);
            uint32_t a1 = f2tf(odd ? h1 : h0);
            uint32_t a2 = f2tf(odd ? f1 : f0);
            uint32_t a3 = f2tf(odd ? i1 : i0);

            #pragma unroll
            for (int nt = 0; nt < 8; nt++) {
                int vi = (kc * 8 + t) * VP + nt * 8 + g;
                uint32_t bh0 = __float_as_uint(Vt[vi]);
                uint32_t bh1 = __float_as_uint(Vt[vi + 4 * VP]);
                mma_tf32(O[nt], a0, a1, a2, a3, bh0, bh1);
            }
        }
    }

    // ---- epilogue ----
    int b = bh >> 4;
    int h = bh & 15;
    float inv0 = 1.f / l0;
    float inv1 = 1.f / l1;
    int srow = qt * 128 + wm + g;
    size_t base0 = ((size_t)(b * S_ + srow) * H_ + h) * HD_;
    size_t base1 = base0 + (size_t)8 * H_ * HD_;
    #pragma unroll
    for (int nt = 0; nt < 8; nt++) {
        int col = nt * 8 + 2 * t;
        *(float2*)&out[base0 + col] = make_float2(O[nt][0] * inv0, O[nt][1] * inv0);
        *(float2*)&out[base1 + col] = make_float2(O[nt][2] * inv1, O[nt][3] * inv1);
    }
}

extern "C" void kernel_launch(void* const* d_in, const int* in_sizes, int n_in,
                              void* d_out, int out_size)
{
    const float* hs = (const float*)d_in[0];
    const float* w  = (const float*)d_in[1];
    const float* qb = (const float*)d_in[2];
    const float* vb = (const float*)d_in[3];
    float* out = (float*)d_out;

    dim3 g1(N3_ / 128, M_ / 128);   // 24 x 32
    qkv_mma_kernel<<<g1, 256>>>(hs, w, qb, vb);

    cudaFuncSetAttribute(attn9_kernel,
                         cudaFuncAttributeMaxDynamicSharedMemorySize, ATTN_SMEM_BYTES);
    dim3 g2(S_ / 128, B_ * H_);     // 16 x 32
    attn9_kernel<<<g2, 256, ATTN_SMEM_BYTES>>>(out);
}

// round 15
// speedup vs baseline: 1.0337x; 1.0337x over previous
#include <cuda_runtime.h>
#include <math.h>
#include <stdint.h>

#define B_  2
#define S_  2048
#define D_  1024
#define H_  16
#define HD_ 64
#define M_  (B_ * S_)    // 4096
#define N3_ (3 * D_)     // 3072

// Scratch for Q/K/V in (b*H+h, s, e) layout. All tf32-rounded.
__device__ float g_Q[(size_t)M_ * D_];      // tf32-rounded, pre-scaled by QSCALE
__device__ float g_K[(size_t)M_ * D_];      // tf32-rounded
__device__ float g_V[(size_t)M_ * D_];      // tf32-rounded

// ---------------------------------------------------------------------------
// TF32 helpers
// ---------------------------------------------------------------------------
__device__ __forceinline__ uint32_t f2tf(float x) {
    uint32_t r;
    asm("cvt.rna.tf32.f32 %0, %1;" : "=r"(r) : "f"(x));
    return r;
}
__device__ __forceinline__ float tf32r(float x) {
    uint32_t r;
    asm("cvt.rna.tf32.f32 %0, %1;" : "=r"(r) : "f"(x));
    return __uint_as_float(r);
}
__device__ __forceinline__ float ex2(float x) {
    float r;
    asm("ex2.approx.f32 %0, %1;" : "=f"(r) : "f"(x));
    return r;
}
__device__ __forceinline__ void mma_tf32(float c[4],
    uint32_t a0, uint32_t a1, uint32_t a2, uint32_t a3,
    uint32_t b0, uint32_t b1)
{
    asm volatile(
        "mma.sync.aligned.m16n8k8.row.col.f32.tf32.tf32.f32 "
        "{%0,%1,%2,%3}, {%4,%5,%6,%7}, {%8,%9}, {%0,%1,%2,%3};"
        : "+f"(c[0]), "+f"(c[1]), "+f"(c[2]), "+f"(c[3])
        : "r"(a0), "r"(a1), "r"(a2), "r"(a3), "r"(b0), "r"(b1));
}

// Q scale: 1/sqrt(64) * log2(e) -> scores in log2 domain, softmax via ex2
#define QSCALE 0.1803368801111204f

// ---------------------------------------------------------------------------
// Kernel 1: QKV projection, single-pass TF32 MMA (UNCHANGED from R12 — 217us).
// ---------------------------------------------------------------------------
#define GP_A 20
#define GP_W 136

__global__ __launch_bounds__(256, 2) void qkv_mma_kernel(
    const float* __restrict__ A, const float* __restrict__ W,
    const float* __restrict__ qbias, const float* __restrict__ vbias)
{
    __shared__ float Ahi[128 * GP_A];
    __shared__ float Whi[16 * GP_W];

    const int tid  = threadIdx.x;
    const int warp = tid >> 5;
    const int lane = tid & 31;
    const int g    = lane >> 2;
    const int t    = lane & 3;
    const int bm   = blockIdx.y * 128;
    const int bn   = blockIdx.x * 128;
    const int warpM = (warp >> 1) * 32;
    const int warpN = (warp & 1) * 64;

    float C[2][8][4];
    #pragma unroll
    for (int mf = 0; mf < 2; mf++)
        #pragma unroll
        for (int nf = 0; nf < 8; nf++)
            #pragma unroll
            for (int j = 0; j < 4; j++) C[mf][nf][j] = 0.f;

    int arow[2], acg[2], wkk[2], wnn[2];
    float4 pa[2], pw[2];
    #pragma unroll
    for (int i = 0; i < 2; i++) {
        int idx = tid + i * 256;
        arow[i] = idx >> 2;
        acg[i]  = (idx & 3) << 2;
        wkk[i]  = idx >> 5;
        wnn[i]  = (idx & 31) << 2;
        pa[i] = *(const float4*)(A + (size_t)(bm + arow[i]) * D_ + acg[i]);
        pw[i] = *(const float4*)(W + (size_t)wkk[i] * N3_ + bn + wnn[i]);
    }

    for (int k0 = 0; k0 < D_ / 16; k0++) {
        __syncthreads();

        #pragma unroll
        for (int i = 0; i < 2; i++) {
            float4 x = pa[i];
            *(float4*)&Ahi[arow[i] * GP_A + acg[i]] =
                make_float4(tf32r(x.x), tf32r(x.y), tf32r(x.z), tf32r(x.w));
            float4 y = pw[i];
            *(float4*)&Whi[wkk[i] * GP_W + wnn[i]] =
                make_float4(tf32r(y.x), tf32r(y.y), tf32r(y.z), tf32r(y.w));
        }
        __syncthreads();

        if (k0 < D_ / 16 - 1) {
            #pragma unroll
            for (int i = 0; i < 2; i++) {
                pa[i] = *(const float4*)(A + (size_t)(bm + arow[i]) * D_
                                           + (k0 + 1) * 16 + acg[i]);
                pw[i] = *(const float4*)(W + (size_t)((k0 + 1) * 16 + wkk[i]) * N3_
                                           + bn + wnn[i]);
            }
        }

        #pragma unroll
        for (int kc = 0; kc < 2; kc++) {
            uint32_t ah[2][4];
            #pragma unroll
            for (int mf = 0; mf < 2; mf++) {
                int r0 = (warpM + mf * 16 + g) * GP_A + kc * 8 + t;
                ah[mf][0] = __float_as_uint(Ahi[r0]);
                ah[mf][1] = __float_as_uint(Ahi[r0 + 8 * GP_A]);
                ah[mf][2] = __float_as_uint(Ahi[r0 + 4]);
                ah[mf][3] = __float_as_uint(Ahi[r0 + 8 * GP_A + 4]);
            }
            #pragma unroll
            for (int nf = 0; nf < 8; nf++) {
                int n  = warpN + nf * 8 + g;
                int kb = (kc * 8 + t) * GP_W + n;
                uint32_t bh0 = __float_as_uint(Whi[kb]);
                uint32_t bh1 = __float_as_uint(Whi[kb + 4 * GP_W]);
                #pragma unroll
                for (int mf = 0; mf < 2; mf++)
                    mma_tf32(C[mf][nf], ah[mf][0], ah[mf][1], ah[mf][2], ah[mf][3], bh0, bh1);
            }
        }
    }

    const int which = bn >> 10;
    #pragma unroll
    for (int mf = 0; mf < 2; mf++) {
        int mrow = bm + warpM + mf * 16 + g;
        int b = mrow >> 11;
        int s = mrow & (S_ - 1);
        #pragma unroll
        for (int nf = 0; nf < 8; nf++) {
            int ncol = bn + warpN + nf * 8 + 2 * t;
            int d = ncol & (D_ - 1);
            int h = d >> 6;
            int e = d & 63;
            size_t i0 = ((size_t)(b * H_ + h) * S_ + s) * HD_ + e;
            size_t i1 = i0 + 8 * HD_;
            float c0 = C[mf][nf][0], c1 = C[mf][nf][1];
            float c2 = C[mf][nf][2], c3 = C[mf][nf][3];
            if (which == 0) {
                float b0 = qbias[d], b1 = qbias[d + 1];
                *(float2*)&g_Q[i0] = make_float2(tf32r((c0 + b0) * QSCALE),
                                                 tf32r((c1 + b1) * QSCALE));
                *(float2*)&g_Q[i1] = make_float2(tf32r((c2 + b0) * QSCALE),
                                                 tf32r((c3 + b1) * QSCALE));
            } else if (which == 1) {
                *(float2*)&g_K[i0] = make_float2(tf32r(c0), tf32r(c1));
                *(float2*)&g_K[i1] = make_float2(tf32r(c2), tf32r(c3));
            } else {
                float b0 = vbias[d], b1 = vbias[d + 1];
                *(float2*)&g_V[i0] = make_float2(tf32r(c0 + b0), tf32r(c1 + b1));
                *(float2*)&g_V[i1] = make_float2(tf32r(c2 + b0), tf32r(c3 + b1));
            }
        }
    }
}

// ---------------------------------------------------------------------------
// Kernel 2: flash attention — champion R12 shape (4 warps x M=32, Br=128,
// Bc=64, single-MMA QK/PV) with FRAGMENT-PACKED smem layouts:
//   QF[kc][mt][lane] float4 (a0,a1,a2,a3)  -> 1 LDS.128 per Q fragment
//   KF[kc][nt][lane] float2 (b0,b1)        -> 1 LDS.64 per K fragment
//   VF[kc][nt][lane] float2 (b0,b1)        -> 1 LDS.64 per V fragment
// Main-loop LDS issues per warp-tile: 320 -> 144. Values/MMA order identical
// to R12 attn7 -> rel_err must be unchanged.
// Plane pads: QPK=1028, KPL=516 (scatter STS spread over 16 banks), VPL=528.
// smem = (8224 + 4128 + 4224) * 4 = 66304 B -> 2 blocks/SM.
// ---------------------------------------------------------------------------
#define QPK 1028              // floats per kc-plane of QF (8 mt * 128 + 4 pad)
#define KPL 516               // floats per kc-plane of KF (8 nt * 64 + 4 pad)
#define VPL 528               // floats per kc-plane of VF (8 nt * 66)
#define VNB 66                // floats per (kc,nt) block of VF
#define SM_QF (8 * QPK)       // 8224
#define SM_KF (8 * KPL)       // 4128
#define SM_VF (8 * VPL)       // 4224
#define ATTN_SMEM_BYTES ((SM_QF + SM_KF + SM_VF) * (int)sizeof(float)) // 66304

__global__ __launch_bounds__(128, 2) void attn10_kernel(float* __restrict__ out)
{
    extern __shared__ float sm[];
    float* QF = sm;                  // packed Q fragments
    float* KF = sm + SM_QF;          // packed K fragments
    float* VF = sm + SM_QF + SM_KF;  // packed V fragments

    const int tid  = threadIdx.x;
    const int warp = tid >> 5;
    const int lane = tid & 31;
    const int g    = lane >> 2;
    const int t    = lane & 3;
    const int bh   = blockIdx.y;
    const int qt   = blockIdx.x;

    const float* Qg = g_Q + ((size_t)bh * S_ + qt * 128) * HD_;
    const float* Kg = g_K + (size_t)bh * S_ * HD_;
    const float* Vg = g_V + (size_t)bh * S_ * HD_;

    // ---- Q prologue: pack 128x64 into QF ----
    // element (r,c): mt=r>>4, g'=r&7, comp=(r&8)>>3 + 2*((c&4)>>2), kc=c>>3, t'=c&3
    // QF float index = kc*QPK + mt*128 + (g'*4 + t')*4 + comp
    #pragma unroll
    for (int i = 0; i < 16; i++) {
        int idx = tid + i * 128;
        int r   = idx >> 4;
        int c0  = (idx & 15) << 2;
        float4 x = *(const float4*)(Qg + r * HD_ + c0);
        int mt = r >> 4;
        int gq = r & 7;
        int cb = (r & 8) >> 3;             // comp base (row upper/lower)
        int kc = c0 >> 3;
        int ch = ((c0 & 4) >> 2) * 2;      // comp high (k lower/upper half)
        int base = kc * QPK + mt * 128 + gq * 16 + cb + ch;
        QF[base]      = x.x;
        QF[base + 4]  = x.y;
        QF[base + 8]  = x.z;
        QF[base + 12] = x.w;
    }

    // staging coordinates for K/V tiles (fixed per thread)
    // K element (r,c): nt=r>>3, g2=r&7, kc=c>>3, comp=(c&4)>>2, t'=c&3
    //   KF idx = kc*KPL + nt*64 + (g2*4 + t')*2 + comp   (stride 2 over t')
    // V element (r,c): kc=r>>3, t'=r&3, comp=(r&4)>>2, nt=c>>3, g'=c&7
    //   VF idx = kc*VPL + nt*VNB + (g'*4 + t')*2 + comp  (stride 8 over g')
    int kbase[8], vbase[8], goff[8];
    #pragma unroll
    for (int i = 0; i < 8; i++) {
        int idx = tid + i * 128;
        int r   = idx >> 4;               // 0..63
        int c0  = (idx & 15) << 2;        // 0,4,...,60
        goff[i] = r * HD_ + c0;
        kbase[i] = (c0 >> 3) * KPL + (r >> 3) * 64 + (r & 7) * 8 + ((c0 & 4) >> 2);
        vbase[i] = (r >> 3) * VPL + (c0 >> 3) * VNB + (c0 & 7) * 8 + (r & 3) * 2
                 + ((r & 4) >> 2);
    }

    float m[2][2], l[2][2];
    #pragma unroll
    for (int mf = 0; mf < 2; mf++) {
        m[mf][0] = -INFINITY; m[mf][1] = -INFINITY;
        l[mf][0] = 0.f;       l[mf][1] = 0.f;
    }
    float O[2][8][4];
    #pragma unroll
    for (int mf = 0; mf < 2; mf++)
        #pragma unroll
        for (int nt = 0; nt < 8; nt++)
            #pragma unroll
            for (int j = 0; j < 4; j++) O[mf][nt][j] = 0.f;

    const int mt0 = warp * 2;   // this warp's two 16-row fragment tiles

    for (int kt = 0; kt < S_ / 64; kt++) {
        __syncthreads();

        // ---- stage K and V into packed layouts ----
        const float* Kt = Kg + (size_t)kt * 64 * HD_;
        const float* Vp = Vg + (size_t)kt * 64 * HD_;
        #pragma unroll
        for (int i = 0; i < 8; i++) {
            float4 kx = *(const float4*)(Kt + goff[i]);
            float4 vx = *(const float4*)(Vp + goff[i]);
            int kb = kbase[i];
            KF[kb]     = kx.x;
            KF[kb + 2] = kx.y;
            KF[kb + 4] = kx.z;
            KF[kb + 6] = kx.w;
            int vb = vbase[i];
            VF[vb]      = vx.x;
            VF[vb + 8]  = vx.y;
            VF[vb + 16] = vx.z;
            VF[vb + 24] = vx.w;
        }
        __syncthreads();

        // ---- scores (log2 domain): 1 MMA; Q = LDS.128, K = LDS.64 ----
        float Sf[2][8][4];
        #pragma unroll
        for (int mf = 0; mf < 2; mf++)
            #pragma unroll
            for (int nt = 0; nt < 8; nt++)
                #pragma unroll
                for (int j = 0; j < 4; j++) Sf[mf][nt][j] = 0.f;

        #pragma unroll
        for (int kc = 0; kc < 8; kc++) {
            uint32_t ah[2][4];
            #pragma unroll
            for (int mf = 0; mf < 2; mf++) {
                float4 qa = *(const float4*)&QF[kc * QPK + (mt0 + mf) * 128 + lane * 4];
                ah[mf][0] = __float_as_uint(qa.x);
                ah[mf][1] = __float_as_uint(qa.y);
                ah[mf][2] = __float_as_uint(qa.z);
                ah[mf][3] = __float_as_uint(qa.w);
            }
            #pragma unroll
            for (int nt = 0; nt < 8; nt++) {
                float2 kk = *(const float2*)&KF[kc * KPL + nt * 64 + lane * 2];
                uint32_t bh0 = __float_as_uint(kk.x);
                uint32_t bh1 = __float_as_uint(kk.y);
                #pragma unroll
                for (int mf = 0; mf < 2; mf++)
                    mma_tf32(Sf[mf][nt], ah[mf][0], ah[mf][1], ah[mf][2], ah[mf][3], bh0, bh1);
            }
        }

        // ---- online softmax (base-2) ----
        #pragma unroll
        for (int mf = 0; mf < 2; mf++) {
            float mx0 = -INFINITY, mx1 = -INFINITY;
            #pragma unroll
            for (int nt = 0; nt < 8; nt++) {
                mx0 = fmaxf(mx0, fmaxf(Sf[mf][nt][0], Sf[mf][nt][1]));
                mx1 = fmaxf(mx1, fmaxf(Sf[mf][nt][2], Sf[mf][nt][3]));
            }
            mx0 = fmaxf(mx0, __shfl_xor_sync(0xffffffffu, mx0, 1));
            mx0 = fmaxf(mx0, __shfl_xor_sync(0xffffffffu, mx0, 2));
            mx1 = fmaxf(mx1, __shfl_xor_sync(0xffffffffu, mx1, 1));
            mx1 = fmaxf(mx1, __shfl_xor_sync(0xffffffffu, mx1, 2));

            float mn0 = fmaxf(m[mf][0], mx0);
            float mn1 = fmaxf(m[mf][1], mx1);
            float alp0 = ex2(m[mf][0] - mn0);
            float alp1 = ex2(m[mf][1] - mn1);

            float ls0 = 0.f, ls1 = 0.f;
            #pragma unroll
            for (int nt = 0; nt < 8; nt++) {
                Sf[mf][nt][0] = ex2(Sf[mf][nt][0] - mn0);
                Sf[mf][nt][1] = ex2(Sf[mf][nt][1] - mn0);
                Sf[mf][nt][2] = ex2(Sf[mf][nt][2] - mn1);
                Sf[mf][nt][3] = ex2(Sf[mf][nt][3] - mn1);
                ls0 += Sf[mf][nt][0] + Sf[mf][nt][1];
                ls1 += Sf[mf][nt][2] + Sf[mf][nt][3];
            }
            ls0 += __shfl_xor_sync(0xffffffffu, ls0, 1);
            ls0 += __shfl_xor_sync(0xffffffffu, ls0, 2);
            ls1 += __shfl_xor_sync(0xffffffffu, ls1, 1);
            ls1 += __shfl_xor_sync(0xffffffffu, ls1, 2);

            l[mf][0] = l[mf][0] * alp0 + ls0;  m[mf][0] = mn0;
            l[mf][1] = l[mf][1] * alp1 + ls1;  m[mf][1] = mn1;

            #pragma unroll
            for (int nt = 0; nt < 8; nt++) {
                O[mf][nt][0] *= alp0;  O[mf][nt][1] *= alp0;
                O[mf][nt][2] *= alp1;  O[mf][nt][3] *= alp1;
            }
        }

        // ---- O += P @ V  (P tf32 via shuffles, V = LDS.64) ----
        const int src0 = (lane & ~3) + (t >> 1);
        const int src2 = src0 + 2;
        const bool odd = (t & 1);

        #pragma unroll
        for (int kc = 0; kc < 8; kc++) {
            uint32_t a[2][4];
            #pragma unroll
            for (int mf = 0; mf < 2; mf++) {
                float e0 = __shfl_sync(0xffffffffu, Sf[mf][kc][0], src0);
                float e1 = __shfl_sync(0xffffffffu, Sf[mf][kc][1], src0);
                float f0 = __shfl_sync(0xffffffffu, Sf[mf][kc][0], src2);
                float f1 = __shfl_sync(0xffffffffu, Sf[mf][kc][1], src2);
                float h0 = __shfl_sync(0xffffffffu, Sf[mf][kc][2], src0);
                float h1 = __shfl_sync(0xffffffffu, Sf[mf][kc][3], src0);
                float i0 = __shfl_sync(0xffffffffu, Sf[mf][kc][2], src2);
                float i1 = __shfl_sync(0xffffffffu, Sf[mf][kc][3], src2);
                a[mf][0] = f2tf(odd ? e1 : e0);
                a[mf][1] = f2tf(odd ? h1 : h0);
                a[mf][2] = f2tf(odd ? f1 : f0);
                a[mf][3] = f2tf(odd ? i1 : i0);
            }
            #pragma unroll
            for (int nt = 0; nt < 8; nt++) {
                float2 vv = *(const float2*)&VF[kc * VPL + nt * VNB + lane * 2];
                uint32_t bh0 = __float_as_uint(vv.x);
                uint32_t bh1 = __float_as_uint(vv.y);
                #pragma unroll
                for (int mf = 0; mf < 2; mf++)
                    mma_tf32(O[mf][nt], a[mf][0], a[mf][1], a[mf][2], a[mf][3], bh0, bh1);
            }
        }
    }

    // ---- epilogue ----
    int b = bh >> 4;
    int h = bh & 15;
    #pragma unroll
    for (int mf = 0; mf < 2; mf++) {
        float inv0 = 1.f / l[mf][0];
        float inv1 = 1.f / l[mf][1];
        int srow = qt * 128 + warp * 32 + mf * 16 + g;
        size_t base0 = ((size_t)(b * S_ + srow) * H_ + h) * HD_;
        size_t base1 = base0 + (size_t)8 * H_ * HD_;
        #pragma unroll
        for (int nt = 0; nt < 8; nt++) {
            int col = nt * 8 + 2 * t;
            *(float2*)&out[base0 + col] =
                make_float2(O[mf][nt][0] * inv0, O[mf][nt][1] * inv0);
            *(float2*)&out[base1 + col] =
                make_float2(O[mf][nt][2] * inv1, O[mf][nt][3] * inv1);
        }
    }
}

extern "C" void kernel_launch(void* const* d_in, const int* in_sizes, int n_in,
                              void* d_out, int out_size)
{
    const float* hs = (const float*)d_in[0];
    const float* w  = (const float*)d_in[1];
    const float* qb = (const float*)d_in[2];
    const float* vb = (const float*)d_in[3];
    float* out = (float*)d_out;

    dim3 g1(N3_ / 128, M_ / 128);   // 24 x 32
    qkv_mma_kernel<<<g1, 256>>>(hs, w, qb, vb);

    cudaFuncSetAttribute(attn10_kernel,
                         cudaFuncAttributeMaxDynamicSharedMemorySize, ATTN_SMEM_BYTES);
    dim3 g2(S_ / 128, B_ * H_);     // 16 x 32
    attn10_kernel<<<g2, 128, ATTN_SMEM_BYTES>>>(out);
}

// round 16
// speedup vs baseline: 1.1178x; 1.0813x over previous
#include <cuda_runtime.h>
#include <math.h>
#include <stdint.h>

#define B_  2
#define S_  2048
#define D_  1024
#define H_  16
#define HD_ 64
#define M_  (B_ * S_)    // 4096
#define N3_ (3 * D_)     // 3072

// Scratch for Q/K/V in (b*H+h, s, e) layout. All tf32-rounded.
__device__ float g_Q[(size_t)M_ * D_];      // tf32-rounded, pre-scaled by QSCALE
__device__ float g_K[(size_t)M_ * D_];      // tf32-rounded
__device__ float g_V[(size_t)M_ * D_];      // tf32-rounded

// ---------------------------------------------------------------------------
// TF32 helpers
// ---------------------------------------------------------------------------
__device__ __forceinline__ uint32_t f2tf(float x) {
    uint32_t r;
    asm("cvt.rna.tf32.f32 %0, %1;" : "=r"(r) : "f"(x));
    return r;
}
__device__ __forceinline__ float tf32r(float x) {
    uint32_t r;
    asm("cvt.rna.tf32.f32 %0, %1;" : "=r"(r) : "f"(x));
    return __uint_as_float(r);
}
__device__ __forceinline__ float ex2(float x) {
    float r;
    asm("ex2.approx.f32 %0, %1;" : "=f"(r) : "f"(x));
    return r;
}
__device__ __forceinline__ void mma_tf32(float c[4],
    uint32_t a0, uint32_t a1, uint32_t a2, uint32_t a3,
    uint32_t b0, uint32_t b1)
{
    asm volatile(
        "mma.sync.aligned.m16n8k8.row.col.f32.tf32.tf32.f32 "
        "{%0,%1,%2,%3}, {%4,%5,%6,%7}, {%8,%9}, {%0,%1,%2,%3};"
        : "+f"(c[0]), "+f"(c[1]), "+f"(c[2]), "+f"(c[3])
        : "r"(a0), "r"(a1), "r"(a2), "r"(a3), "r"(b0), "r"(b1));
}

// Q scale: 1/sqrt(64) * log2(e) -> scores in log2 domain, softmax via ex2
#define QSCALE 0.1803368801111204f

// ---------------------------------------------------------------------------
// Kernel 1: QKV projection, single-pass TF32 MMA, BK=32 (32 slabs instead of
// 64): half the barriers/stage transitions, same MMA total in the same
// global k-order (accumulation sequence identical -> bit-identical output).
// No reg prefetch (would breach 128-reg ceiling at 512 thr/SM); staging LDG
// latency covered by the co-resident block's MMA phase.
// BM=128, BN=128, BK=32, 256 threads, warps 4(M)x2(N), warp tile 32x64.
// smem: Ahi [128][36] + Whi [32][136] = 35840 B static -> 2 blocks/SM.
// ---------------------------------------------------------------------------
#define GP_A 36
#define GP_W 136

__global__ __launch_bounds__(256, 2) void qkv_mma_kernel(
    const float* __restrict__ A, const float* __restrict__ W,
    const float* __restrict__ qbias, const float* __restrict__ vbias)
{
    __shared__ float Ahi[128 * GP_A];   // 18432 B
    __shared__ float Whi[32 * GP_W];    // 17408 B

    const int tid  = threadIdx.x;
    const int warp = tid >> 5;
    const int lane = tid & 31;
    const int g    = lane >> 2;
    const int t    = lane & 3;
    const int bm   = blockIdx.y * 128;
    const int bn   = blockIdx.x * 128;
    const int warpM = (warp >> 1) * 32;
    const int warpN = (warp & 1) * 64;

    float C[2][8][4];
    #pragma unroll
    for (int mf = 0; mf < 2; mf++)
        #pragma unroll
        for (int nf = 0; nf < 8; nf++)
            #pragma unroll
            for (int j = 0; j < 4; j++) C[mf][nf][j] = 0.f;

    // staging coords: 4 float4 A + 4 float4 W per thread per slab
    int arow[4], acol[4], wrow[4], wcol[4];
    #pragma unroll
    for (int i = 0; i < 4; i++) {
        int idx = tid + i * 256;          // 0..1023
        arow[i] = idx >> 3;               // 0..127 (8 float4 per 32-float A row)
        acol[i] = (idx & 7) << 2;         // 0..28
        wrow[i] = idx >> 5;               // 0..31 (32 float4 per 128-float W row)
        wcol[i] = (idx & 31) << 2;        // 0..124
    }

    const int NS = D_ / 32;   // 32 slabs

    for (int k0 = 0; k0 < NS; k0++) {
        __syncthreads();   // previous MMA phase done reading smem

        #pragma unroll
        for (int i = 0; i < 4; i++) {
            float4 x = *(const float4*)(A + (size_t)(bm + arow[i]) * D_
                                          + k0 * 32 + acol[i]);
            *(float4*)&Ahi[arow[i] * GP_A + acol[i]] =
                make_float4(tf32r(x.x), tf32r(x.y), tf32r(x.z), tf32r(x.w));
            float4 y = *(const float4*)(W + (size_t)(k0 * 32 + wrow[i]) * N3_
                                          + bn + wcol[i]);
            *(float4*)&Whi[wrow[i] * GP_W + wcol[i]] =
                make_float4(tf32r(y.x), tf32r(y.y), tf32r(y.z), tf32r(y.w));
        }
        __syncthreads();

        #pragma unroll
        for (int kc = 0; kc < 4; kc++) {
            uint32_t ah[2][4];
            #pragma unroll
            for (int mf = 0; mf < 2; mf++) {
                int r0 = (warpM + mf * 16 + g) * GP_A + kc * 8 + t;
                ah[mf][0] = __float_as_uint(Ahi[r0]);
                ah[mf][1] = __float_as_uint(Ahi[r0 + 8 * GP_A]);
                ah[mf][2] = __float_as_uint(Ahi[r0 + 4]);
                ah[mf][3] = __float_as_uint(Ahi[r0 + 8 * GP_A + 4]);
            }
            #pragma unroll
            for (int nf = 0; nf < 8; nf++) {
                int n  = warpN + nf * 8 + g;
                int kb = (kc * 8 + t) * GP_W + n;
                uint32_t bh0 = __float_as_uint(Whi[kb]);
                uint32_t bh1 = __float_as_uint(Whi[kb + 4 * GP_W]);
                #pragma unroll
                for (int mf = 0; mf < 2; mf++)
                    mma_tf32(C[mf][nf], ah[mf][0], ah[mf][1], ah[mf][2], ah[mf][3], bh0, bh1);
            }
        }
    }

    // Epilogue: scatter into (b*H+h, s, e); all three tf32-rounded.
    const int which = bn >> 10;
    #pragma unroll
    for (int mf = 0; mf < 2; mf++) {
        int mrow = bm + warpM + mf * 16 + g;
        int b = mrow >> 11;
        int s = mrow & (S_ - 1);
        #pragma unroll
        for (int nf = 0; nf < 8; nf++) {
            int ncol = bn + warpN + nf * 8 + 2 * t;
            int d = ncol & (D_ - 1);
            int h = d >> 6;
            int e = d & 63;
            size_t i0 = ((size_t)(b * H_ + h) * S_ + s) * HD_ + e;
            size_t i1 = i0 + 8 * HD_;
            float c0 = C[mf][nf][0], c1 = C[mf][nf][1];
            float c2 = C[mf][nf][2], c3 = C[mf][nf][3];
            if (which == 0) {
                float b0 = qbias[d], b1 = qbias[d + 1];
                *(float2*)&g_Q[i0] = make_float2(tf32r((c0 + b0) * QSCALE),
                                                 tf32r((c1 + b1) * QSCALE));
                *(float2*)&g_Q[i1] = make_float2(tf32r((c2 + b0) * QSCALE),
                                                 tf32r((c3 + b1) * QSCALE));
            } else if (which == 1) {
                *(float2*)&g_K[i0] = make_float2(tf32r(c0), tf32r(c1));
                *(float2*)&g_K[i1] = make_float2(tf32r(c2), tf32r(c3));
            } else {
                float b0 = vbias[d], b1 = vbias[d + 1];
                *(float2*)&g_V[i0] = make_float2(tf32r(c0 + b0), tf32r(c1 + b1));
                *(float2*)&g_V[i1] = make_float2(tf32r(c2 + b0), tf32r(c3 + b1));
            }
        }
    }
}

// ---------------------------------------------------------------------------
// Kernel 2: flash attention — the R12 CHAMPION attn7, verbatim (264.7us;
// three alternative formulations all measured worse; frozen).
// Block = 128 threads (4 warps), warp tile M=32, Br=128, Bc=64.
// Single-MMA QK/PV; K/V/Q arrive tf32-rounded; softmax base-2 via ex2.
// smem: Qs [128][68] + Khi [64][68] + Vt [64][72] = 70656 B -> 2 blk/SM.
// ---------------------------------------------------------------------------
#define QP 68
#define KP 68
#define VP 72
#define SM_Q (128 * QP)
#define SM_K (64 * KP)
#define SM_V (64 * VP)
#define ATTN_SMEM_BYTES ((SM_Q + SM_K + SM_V) * (int)sizeof(float))   // 70656

__global__ __launch_bounds__(128, 2) void attn7_kernel(float* __restrict__ out)
{
    extern __shared__ float sm[];
    float* Qs  = sm;             // [128][QP] tf32-rounded, pre-scaled
    float* Khi = Qs + SM_Q;      // [64][KP] tf32-rounded
    float* Vt  = Khi + SM_K;     // [64][VP] tf32-rounded

    const int tid  = threadIdx.x;
    const int warp = tid >> 5;
    const int lane = tid & 31;
    const int g    = lane >> 2;
    const int t    = lane & 3;
    const int wm   = warp * 32;
    const int bh   = blockIdx.y;
    const int qt   = blockIdx.x;

    const float* Qg = g_Q + ((size_t)bh * S_ + qt * 128) * HD_;
    const float* Kg = g_K + (size_t)bh * S_ * HD_;
    const float* Vg = g_V + (size_t)bh * S_ * HD_;

    #pragma unroll
    for (int i = 0; i < 16; i++) {
        int idx = tid + i * 128;
        int row = idx >> 4;
        int col = (idx & 15) << 2;
        *(float4*)&Qs[row * QP + col] = *(const float4*)(Qg + row * HD_ + col);
    }

    float m[2][2], l[2][2];
    #pragma unroll
    for (int mf = 0; mf < 2; mf++) {
        m[mf][0] = -INFINITY; m[mf][1] = -INFINITY;
        l[mf][0] = 0.f;       l[mf][1] = 0.f;
    }
    float O[2][8][4];
    #pragma unroll
    for (int mf = 0; mf < 2; mf++)
        #pragma unroll
        for (int nt = 0; nt < 8; nt++)
            #pragma unroll
            for (int j = 0; j < 4; j++) O[mf][nt][j] = 0.f;

    for (int kt = 0; kt < S_ / 64; kt++) {
        __syncthreads();

        // ---- stage K and V: pure float4 copies (data already tf32) ----
        const float* Kt = Kg + (size_t)kt * 64 * HD_;
        const float* Vp = Vg + (size_t)kt * 64 * HD_;
        #pragma unroll
        for (int i = 0; i < 8; i++) {
            int idx = tid + i * 128;
            int row = idx >> 4;
            int col = (idx & 15) << 2;
            *(float4*)&Khi[row * KP + col] = *(const float4*)(Kt + row * HD_ + col);
            *(float4*)&Vt[row * VP + col]  = *(const float4*)(Vp + row * HD_ + col);
        }
        __syncthreads();

        // ---- scores (log2 domain): 1 MMA, fragments pure LDS ----
        float Sf[2][8][4];
        #pragma unroll
        for (int mf = 0; mf < 2; mf++)
            #pragma unroll
            for (int nt = 0; nt < 8; nt++)
                #pragma unroll
                for (int j = 0; j < 4; j++) Sf[mf][nt][j] = 0.f;

        #pragma unroll
        for (int kc = 0; kc < 8; kc++) {
            uint32_t ah[2][4];
            #pragma unroll
            for (int mf = 0; mf < 2; mf++) {
                int qi = (wm + mf * 16 + g) * QP + kc * 8 + t;
                ah[mf][0] = __float_as_uint(Qs[qi]);
                ah[mf][1] = __float_as_uint(Qs[qi + 8 * QP]);
                ah[mf][2] = __float_as_uint(Qs[qi + 4]);
                ah[mf][3] = __float_as_uint(Qs[qi + 8 * QP + 4]);
            }
            #pragma unroll
            for (int nt = 0; nt < 8; nt++) {
                int kb = (nt * 8 + g) * KP + kc * 8 + t;
                uint32_t bh0 = __float_as_uint(Khi[kb]);
                uint32_t bh1 = __float_as_uint(Khi[kb + 4]);
                #pragma unroll
                for (int mf = 0; mf < 2; mf++)
                    mma_tf32(Sf[mf][nt], ah[mf][0], ah[mf][1], ah[mf][2], ah[mf][3], bh0, bh1);
            }
        }

        // ---- online softmax (base-2) ----
        #pragma unroll
        for (int mf = 0; mf < 2; mf++) {
            float mx0 = -INFINITY, mx1 = -INFINITY;
            #pragma unroll
            for (int nt = 0; nt < 8; nt++) {
                mx0 = fmaxf(mx0, fmaxf(Sf[mf][nt][0], Sf[mf][nt][1]));
                mx1 = fmaxf(mx1, fmaxf(Sf[mf][nt][2], Sf[mf][nt][3]));
            }
            mx0 = fmaxf(mx0, __shfl_xor_sync(0xffffffffu, mx0, 1));
            mx0 = fmaxf(mx0, __shfl_xor_sync(0xffffffffu, mx0, 2));
            mx1 = fmaxf(mx1, __shfl_xor_sync(0xffffffffu, mx1, 1));
            mx1 = fmaxf(mx1, __shfl_xor_sync(0xffffffffu, mx1, 2));

            float mn0 = fmaxf(m[mf][0], mx0);
            float mn1 = fmaxf(m[mf][1], mx1);
            float alp0 = ex2(m[mf][0] - mn0);
            float alp1 = ex2(m[mf][1] - mn1);

            float ls0 = 0.f, ls1 = 0.f;
            #pragma unroll
            for (int nt = 0; nt < 8; nt++) {
                Sf[mf][nt][0] = ex2(Sf[mf][nt][0] - mn0);
                Sf[mf][nt][1] = ex2(Sf[mf][nt][1] - mn0);
                Sf[mf][nt][2] = ex2(Sf[mf][nt][2] - mn1);
                Sf[mf][nt][3] = ex2(Sf[mf][nt][3] - mn1);
                ls0 += Sf[mf][nt][0] + Sf[mf][nt][1];
                ls1 += Sf[mf][nt][2] + Sf[mf][nt][3];
            }
            ls0 += __shfl_xor_sync(0xffffffffu, ls0, 1);
            ls0 += __shfl_xor_sync(0xffffffffu, ls0, 2);
            ls1 += __shfl_xor_sync(0xffffffffu, ls1, 1);
            ls1 += __shfl_xor_sync(0xffffffffu, ls1, 2);

            l[mf][0] = l[mf][0] * alp0 + ls0;  m[mf][0] = mn0;
            l[mf][1] = l[mf][1] * alp1 + ls1;  m[mf][1] = mn1;

            #pragma unroll
            for (int nt = 0; nt < 8; nt++) {
                O[mf][nt][0] *= alp0;  O[mf][nt][1] *= alp0;
                O[mf][nt][2] *= alp1;  O[mf][nt][3] *= alp1;
            }
        }

        // ---- O += P @ V ----
        const int src0 = (lane & ~3) + (t >> 1);
        const int src2 = src0 + 2;
        const bool odd = (t & 1);

        #pragma unroll
        for (int kc = 0; kc < 8; kc++) {
            uint32_t a[2][4];
            #pragma unroll
            for (int mf = 0; mf < 2; mf++) {
                float e0 = __shfl_sync(0xffffffffu, Sf[mf][kc][0], src0);
                float e1 = __shfl_sync(0xffffffffu, Sf[mf][kc][1], src0);
                float f0 = __shfl_sync(0xffffffffu, Sf[mf][kc][0], src2);
                float f1 = __shfl_sync(0xffffffffu, Sf[mf][kc][1], src2);
                float h0 = __shfl_sync(0xffffffffu, Sf[mf][kc][2], src0);
                float h1 = __shfl_sync(0xffffffffu, Sf[mf][kc][3], src0);
                float i0 = __shfl_sync(0xffffffffu, Sf[mf][kc][2], src2);
                float i1 = __shfl_sync(0xffffffffu, Sf[mf][kc][3], src2);
                a[mf][0] = f2tf(odd ? e1 : e0);
                a[mf][1] = f2tf(odd ? h1 : h0);
                a[mf][2] = f2tf(odd ? f1 : f0);
                a[mf][3] = f2tf(odd ? i1 : i0);
            }
            #pragma unroll
            for (int nt = 0; nt < 8; nt++) {
                int vi = (kc * 8 + t) * VP + nt * 8 + g;
                uint32_t bh0 = __float_as_uint(Vt[vi]);
                uint32_t bh1 = __float_as_uint(Vt[vi + 4 * VP]);
                #pragma unroll
                for (int mf = 0; mf < 2; mf++)
                    mma_tf32(O[mf][nt], a[mf][0], a[mf][1], a[mf][2], a[mf][3], bh0, bh1);
            }
        }
    }

    // ---- epilogue ----
    int b = bh >> 4;
    int h = bh & 15;
    #pragma unroll
    for (int mf = 0; mf < 2; mf++) {
        float inv0 = 1.f / l[mf][0];
        float inv1 = 1.f / l[mf][1];
        int srow = qt * 128 + wm + mf * 16 + g;
        size_t base0 = ((size_t)(b * S_ + srow) * H_ + h) * HD_;
        size_t base1 = base0 + (size_t)8 * H_ * HD_;
        #pragma unroll
        for (int nt = 0; nt < 8; nt++) {
            int col = nt * 8 + 2 * t;
            *(float2*)&out[base0 + col] =
                make_float2(O[mf][nt][0] * inv0, O[mf][nt][1] * inv0);
            *(float2*)&out[base1 + col] =
                make_float2(O[mf][nt][2] * inv1, O[mf][nt][3] * inv1);
        }
    }
}

extern "C" void kernel_launch(void* const* d_in, const int* in_sizes, int n_in,
                              void* d_out, int out_size)
{
    const float* hs = (const float*)d_in[0];
    const float* w  = (const float*)d_in[1];
    const float* qb = (const float*)d_in[2];
    const float* vb = (const float*)d_in[3];
    float* out = (float*)d_out;

    dim3 g1(N3_ / 128, M_ / 128);   // 24 x 32
    qkv_mma_kernel<<<g1, 256>>>(hs, w, qb, vb);

    cudaFuncSetAttribute(attn7_kernel,
                         cudaFuncAttributeMaxDynamicSharedMemorySize, ATTN_SMEM_BYTES);
    dim3 g2(S_ / 128, B_ * H_);     // 16 x 32
    attn7_kernel<<<g2, 128, ATTN_SMEM_BYTES>>>(out);
}